// round 1
// baseline (speedup 1.0000x reference)
#include <cuda_runtime.h>
#include <cstdint>

// Problem constants
#define WW 48
#define HH 48
#define NQ 2304          // W*H query/key positions
#define NHD 8            // heads
#define EE 64            // embed
#define BB 8             // batch
#define CC 512           // B*E fused value columns
#define TW 95            // table width (dx in [-47,47])
#define TT (TW*TW)       // 9025
#define LOG2E 1.4426950408889634f

// Scratch (static device globals -- no runtime allocation allowed)
__device__ float g_S[NHD * TT];          // score table * log2(e)
__device__ float g_cm[NHD * TW * HH];    // column sliding max
__device__ float g_M[NHD * NQ];          // per-(query,head) window max (log2 units)
__device__ float g_Xt[NQ * CC];          // values transposed: [key][b*64+e]
__device__ float g_U[NHD * NQ * CC];     // normalized head outputs: [n][q][b*64+e]
__device__ float g_Wpt[CC * EE];         // W_fc permuted: [f'=n*64+e][eo]

__device__ __forceinline__ float fexp2(float x) {
    float y;
    asm("ex2.approx.ftz.f32 %0, %1;" : "=f"(y) : "f"(x));
    return y;
}

// ---------------------------------------------------------------------------
// Value transpose: Xt[kl][b*64+e] = hs[b][kl][e]
__global__ void k_xt(const float* __restrict__ hs) {
    int o = blockIdx.x * blockDim.x + threadIdx.x;
    if (o >= NQ * CC) return;
    int kl = o / CC;
    int r  = o - kl * CC;
    int b  = r >> 6;
    int e  = r & 63;
    g_Xt[o] = hs[(b * NQ + kl) * EE + e];
}

// W_fc permute: Wpt[(n*64+e)*64 + eo] = W_fc[eo][e*8+n]
__global__ void k_wpt(const float* __restrict__ wfc) {
    int o = blockIdx.x * blockDim.x + threadIdx.x;
    if (o >= CC * EE) return;
    int f  = o >> 6;
    int eo = o & 63;
    int n  = f >> 6;
    int e  = f & 63;
    g_Wpt[o] = wfc[eo * CC + e * NHD + n];
}

// Score table (log2 domain). b_sigma cancels in softmax -> omitted.
__global__ void k_table(const float* __restrict__ wsig) {
    int o = blockIdx.x * blockDim.x + threadIdx.x;
    if (o >= NHD * TT) return;
    int n   = o / TT;
    int r   = o - n * TT;
    int dxi = r / TW;
    int dyi = r - dxi * TW;
    float dx = (float)(dxi - 47);
    float dy = (float)(dyi - 47);
    const float* w = wsig + n * 5;
    float s = w[0] * dx + w[1] * dy + w[2] * dx * dx + w[3] * dy * dy + w[4] * dx * dy;
    g_S[o] = s * LOG2E;
}

// Sliding max over dy (window 48): cm[n][dxi][j] = max_{l<48} S[n][dxi][l-j+47]
__global__ void k_colmax() {
    int o = blockIdx.x * blockDim.x + threadIdx.x;
    if (o >= NHD * TW * HH) return;
    int n   = o / (TW * HH);
    int r   = o - n * TW * HH;
    int dxi = r / HH;
    int j   = r - dxi * HH;
    const float* row = g_S + n * TT + dxi * TW + (47 - j);
    float m = -1e30f;
    #pragma unroll 8
    for (int l = 0; l < HH; l++) m = fmaxf(m, row[l]);
    g_cm[o] = m;
}

// Sliding max over dx: M[n][i*48+j] = max_{k<48} cm[n][k-i+47][j]
__global__ void k_rowmax() {
    int o = blockIdx.x * blockDim.x + threadIdx.x;
    if (o >= NHD * NQ) return;
    int n = o / NQ;
    int r = o - n * NQ;
    int i = r / HH;
    int j = r - i * HH;
    float m = -1e30f;
    #pragma unroll 8
    for (int k = 0; k < WW; k++)
        m = fmaxf(m, g_cm[(n * TW + (k - i + 47)) * HH + j]);
    g_M[o] = m;
}

// ---------------------------------------------------------------------------
// Main fused softmax-attention GEMM.
// Block: head n, 32 queries. Computes U[n][q][0..511] = (P @ Xt)/Z.
#define QT 32
#define KCH 16

__global__ __launch_bounds__(256, 2) void k_attn() {
    __shared__ float Xs[KCH * CC];   // 32 KB value chunk
    __shared__ float Ps[KCH * QT];   // 2 KB prob tile [k][q]
    __shared__ float Zs[QT];

    const int t  = threadIdx.x;
    const int n  = blockIdx.y;
    const int q0 = blockIdx.x * QT;

    // P-producer role: thread handles query qp, key sub-lane ksb (2 keys/chunk)
    const int qp  = t >> 3;                 // 0..31
    const int ksb = t & 7;                  // 0..7
    const int qg  = q0 + qp;
    const int ip  = qg / HH;
    const int jp  = qg - ip * HH;
    const float M2 = g_M[n * NQ + qg];
    const float* St = g_S + n * TT + (47 - ip) * TW + (47 - jp);
    float zpart = 0.f;

    // GEMM consumer role: 4 queries x 16 cols per thread
    const int cg = t & 31;
    const int c0 = cg * 4;
    const int qf = (t >> 5) * 4;
    float acc[4][16];
    #pragma unroll
    for (int a = 0; a < 4; a++)
        #pragma unroll
        for (int b = 0; b < 16; b++) acc[a][b] = 0.f;

    if (t < QT) Zs[t] = 0.f;
    const float4* Xt4 = (const float4*)g_Xt;

    for (int kc = 0; kc < NQ; kc += KCH) {
        __syncthreads();
        // Stage value chunk: 16x512 floats = 2048 float4
        #pragma unroll
        for (int v = 0; v < 8; v++) {
            int fid = v * 256 + t;
            ((float4*)Xs)[fid] = Xt4[kc * (CC / 4) + fid];
        }
        // Produce probabilities for this chunk
        #pragma unroll
        for (int m = 0; m < 2; m++) {
            int kk = ksb * 2 + m;
            int kl = kc + kk;
            int kx = kl / HH;
            int ky = kl - kx * HH;
            float s2 = __ldg(&St[kx * TW + ky]);
            float p = fexp2(s2 - M2);       // <= 1, underflow->0 is exact
            Ps[kk * QT + qp] = p;
            zpart += p;
        }
        __syncthreads();
        // Rank-1 accumulation over the chunk
        #pragma unroll 4
        for (int kk = 0; kk < KCH; kk++) {
            const float4 a4 = *(const float4*)(Ps + kk * QT + qf);
            const float4 b0 = *(const float4*)(Xs + kk * CC + c0);
            const float4 b1 = *(const float4*)(Xs + kk * CC + c0 + 128);
            const float4 b2 = *(const float4*)(Xs + kk * CC + c0 + 256);
            const float4 b3 = *(const float4*)(Xs + kk * CC + c0 + 384);
            float av[4]  = {a4.x, a4.y, a4.z, a4.w};
            float bv[16] = {b0.x, b0.y, b0.z, b0.w,
                            b1.x, b1.y, b1.z, b1.w,
                            b2.x, b2.y, b2.z, b2.w,
                            b3.x, b3.y, b3.z, b3.w};
            #pragma unroll
            for (int mi = 0; mi < 4; mi++)
                #pragma unroll
                for (int ci = 0; ci < 16; ci++)
                    acc[mi][ci] = fmaf(av[mi], bv[ci], acc[mi][ci]);
        }
    }

    atomicAdd(&Zs[qp], zpart);
    __syncthreads();

    #pragma unroll
    for (int mi = 0; mi < 4; mi++) {
        float rz = 1.0f / Zs[qf + mi];
        int q = q0 + qf + mi;
        float* dst = g_U + ((size_t)n * NQ + q) * CC;
        #pragma unroll
        for (int s = 0; s < 4; s++) {
            float4 o;
            o.x = acc[mi][s * 4 + 0] * rz;
            o.y = acc[mi][s * 4 + 1] * rz;
            o.z = acc[mi][s * 4 + 2] * rz;
            o.w = acc[mi][s * 4 + 3] * rz;
            *(float4*)(dst + s * 128 + c0) = o;
        }
    }
}

// ---------------------------------------------------------------------------
// Final projection: out[b,q,eo] = b_fc[eo] + sum_{f'} A[(b,q)][f'] * Wpt[f'][eo]
// A[(b,q)][n*64+e] = U[n][q][b*64+e]. 128 rows x 64 cols per block, k=512.
__global__ __launch_bounds__(256) void k_proj(const float* __restrict__ bfc,
                                              float* __restrict__ out) {
    __shared__ float As[128][33];
    __shared__ float Ws[32][64];
    const int t  = threadIdx.x;
    const int r0 = blockIdx.x * 128;       // global row base (b*NQ+q), never straddles b
    const int b  = r0 / NQ;
    const int q0 = r0 - b * NQ;

    const int rg  = t >> 3;                // 0..31
    const int r_l = rg * 4;
    const int cgp = t & 7;
    const int eo0 = cgp * 8;

    float acc[4][8];
    #pragma unroll
    for (int m = 0; m < 4; m++)
        #pragma unroll
        for (int c = 0; c < 8; c++) acc[m][c] = 0.f;

    for (int fck = 0; fck < CC; fck += 32) {
        __syncthreads();
        {   // load A tile (coalesced over e)
            int fc  = t & 31;
            int rl0 = t >> 5;
            int f = fck + fc;
            int nn = f >> 6;
            int e  = f & 63;
            const float* src = g_U + ((size_t)nn * NQ + q0) * CC + b * EE + e;
            #pragma unroll
            for (int s = 0; s < 16; s++) {
                int rl = rl0 + s * 8;
                As[rl][fc] = src[(size_t)rl * CC];
            }
        }
        {   // load W tile
            int eo = t & 63;
            int f0 = t >> 6;
            #pragma unroll
            for (int s = 0; s < 8; s++) {
                int fcl = f0 + s * 4;
                Ws[fcl][eo] = g_Wpt[(fck + fcl) * EE + eo];
            }
        }
        __syncthreads();
        #pragma unroll 8
        for (int fc = 0; fc < 32; fc++) {
            float a_[4], w_[8];
            #pragma unroll
            for (int m = 0; m < 4; m++) a_[m] = As[r_l + m][fc];
            #pragma unroll
            for (int c = 0; c < 8; c++) w_[c] = Ws[fc][eo0 + c];
            #pragma unroll
            for (int m = 0; m < 4; m++)
                #pragma unroll
                for (int c = 0; c < 8; c++)
                    acc[m][c] = fmaf(a_[m], w_[c], acc[m][c]);
        }
    }
    #pragma unroll
    for (int m = 0; m < 4; m++) {
        int r = r0 + r_l + m;
        #pragma unroll
        for (int c = 0; c < 8; c++)
            out[r * EE + eo0 + c] = acc[m][c] + bfc[eo0 + c];
    }
}

// ---------------------------------------------------------------------------
extern "C" void kernel_launch(void* const* d_in, const int* in_sizes, int n_in,
                              void* d_out, int out_size) {
    const float* hs   = (const float*)d_in[0];   // hidden_states (8,48,48,64)
    // d_in[1] attention_mask: unused. d_in[2] R: unused (recomputed analytically).
    const float* wsig = (const float*)d_in[3];   // W_sigma (8,5)
    // d_in[4] b_sigma: cancels in softmax.
    const float* wfc  = (const float*)d_in[5];   // W_fc (64,512)
    const float* bfc  = (const float*)d_in[6];   // b_fc (64)
    float* out = (float*)d_out;

    k_xt<<<(NQ * CC + 255) / 256, 256>>>(hs);
    k_wpt<<<(CC * EE + 255) / 256, 256>>>(wfc);
    k_table<<<(NHD * TT + 255) / 256, 256>>>(wsig);
    k_colmax<<<(NHD * TW * HH + 255) / 256, 256>>>();
    k_rowmax<<<(NHD * NQ + 255) / 256, 256>>>();

    dim3 ga(NQ / QT, NHD);   // (72, 8)
    k_attn<<<ga, 256>>>();

    k_proj<<<(BB * NQ) / 128, 256>>>(bfc, out);
}

// round 6
// speedup vs baseline: 2.6604x; 2.6604x over previous
#include <cuda_runtime.h>
#include <cuda_bf16.h>
#include <cstdint>

#define WW 48
#define HH 48
#define NQ 2304
#define NHD 8
#define EE 64
#define BB 8
#define CC 512
#define TW 95
#define TT (TW*TW)
#define LOG2E 1.4426950408889634f

#define QT 128            // M per block
#define NCOL 256          // N per block
#define KC 64             // K chunk
#define NCHUNK (NQ/KC)    // 36
#define NW32 (CC*NQ/2)    // b32 words in X operand (589824)

// ---- device scratch (no runtime allocation allowed) ----
__device__ float g_S[NHD * TT];
__device__ float g_cm[NHD * TW * HH];
__device__ float g_M[NHD * NQ];
// 16B-aligned backing for cp.async sources (uint4 guarantees alignment)
__device__ __align__(256) uint4 g_Xbh4[NW32 / 4];   // X hi, fragment-major
__device__ __align__(256) uint4 g_Xbl4[NW32 / 4];   // X lo, fragment-major
__device__ float g_U[NHD * NQ * CC];
__device__ float g_Wpt[CC * EE];

__device__ __forceinline__ float fexp2(float x) {
    float y; asm("ex2.approx.ftz.f32 %0, %1;" : "=f"(y) : "f"(x)); return y;
}
__device__ __forceinline__ uint32_t smem_u32(const void* p) {
    uint32_t a;
    asm("{ .reg .u64 t; cvta.to.shared.u64 t, %1; cvt.u32.u64 %0, t; }" : "=r"(a) : "l"(p));
    return a;
}
__device__ __forceinline__ void cpa16(uint32_t dst, const void* src) {
    asm volatile("cp.async.cg.shared.global [%0], [%1], 16;" :: "r"(dst), "l"(src));
}
__device__ __forceinline__ void mma16816(float* c, const uint4& a, const uint2& b) {
    asm volatile(
        "mma.sync.aligned.m16n8k16.row.col.f32.bf16.bf16.f32 "
        "{%0,%1,%2,%3}, {%4,%5,%6,%7}, {%8,%9}, {%0,%1,%2,%3};"
        : "+f"(c[0]), "+f"(c[1]), "+f"(c[2]), "+f"(c[3])
        : "r"(a.x), "r"(a.y), "r"(a.z), "r"(a.w), "r"(b.x), "r"(b.y));
}

// ---------------------------------------------------------------------------
// Split X into bf16 hi/lo in fragment-major layout:
// word index o: [g 64][kc 36][ks 4][lane 32][word 2]
// lane = n8*4 + (kk&7)/2, word = kk>>3, kk = k%16; c = g*8+n8; value pair (k, k+1)
__global__ void k_xsplit(const float* __restrict__ hs) {
    int o = blockIdx.x * blockDim.x + threadIdx.x;
    if (o >= NW32) return;
    int word = o & 1;
    int lane = (o >> 1) & 31;
    int ks   = (o >> 6) & 3;
    int rem  = o >> 8;
    int kc   = rem % 36;
    int g    = rem / 36;
    int n8   = lane >> 2;
    int kk0  = word * 8 + (lane & 3) * 2;
    int c    = g * 8 + n8;
    int b    = c >> 6, e = c & 63;
    int k    = kc * 64 + ks * 16 + kk0;
    float x0 = hs[(b * NQ + k) * EE + e];
    float x1 = hs[(b * NQ + k + 1) * EE + e];
    __nv_bfloat162 h  = __floats2bfloat162_rn(x0, x1);
    __nv_bfloat162 lo = __floats2bfloat162_rn(x0 - __bfloat162float(h.x),
                                              x1 - __bfloat162float(h.y));
    ((uint32_t*)g_Xbh4)[o] = *(uint32_t*)&h;
    ((uint32_t*)g_Xbl4)[o] = *(uint32_t*)&lo;
}

__global__ void k_wpt(const float* __restrict__ wfc) {
    int o = blockIdx.x * blockDim.x + threadIdx.x;
    if (o >= CC * EE) return;
    int f = o >> 6, eo = o & 63;
    int n = f >> 6, e = f & 63;
    g_Wpt[o] = wfc[eo * CC + e * NHD + n];
}

__global__ void k_table(const float* __restrict__ wsig) {
    int o = blockIdx.x * blockDim.x + threadIdx.x;
    if (o >= NHD * TT) return;
    int n = o / TT, r = o - n * TT;
    int dxi = r / TW, dyi = r - dxi * TW;
    float dx = (float)(dxi - 47), dy = (float)(dyi - 47);
    const float* w = wsig + n * 5;
    g_S[o] = (w[0]*dx + w[1]*dy + w[2]*dx*dx + w[3]*dy*dy + w[4]*dx*dy) * LOG2E;
}

__global__ void k_colmax() {
    int o = blockIdx.x * blockDim.x + threadIdx.x;
    if (o >= NHD * TW * HH) return;
    int n = o / (TW * HH), r = o - n * TW * HH;
    int dxi = r / HH, j = r - dxi * HH;
    const float* row = g_S + n * TT + dxi * TW + (47 - j);
    float m = -1e30f;
    #pragma unroll 8
    for (int l = 0; l < HH; l++) m = fmaxf(m, row[l]);
    g_cm[o] = m;
}

__global__ void k_rowmax() {
    int o = blockIdx.x * blockDim.x + threadIdx.x;
    if (o >= NHD * NQ) return;
    int n = o / NQ, r = o - n * NQ;
    int i = r / HH, j = r - i * HH;
    float m = -1e30f;
    #pragma unroll 8
    for (int k = 0; k < WW; k++)
        m = fmaxf(m, g_cm[(n * TW + (k - i + 47)) * HH + j]);
    g_M[o] = m;
}

// ---------------------------------------------------------------------------
// Dynamic smem layout (bytes)
#define SM_STAB 0                 // 51*95*4 = 19380
#define SM_KIDX 19392             // 2304*2  = 4608
#define SM_Z    24000             // 128*4
#define SM_BUF  24576
#define BUFSZ   98304             // Ah 16K | Al 16K | Bh 32K | Bl 32K
#define OFF_AL  16384
#define OFF_BH  32768
#define OFF_BL  65536
#define SMEM_TOTAL (SM_BUF + 2 * BUFSZ)   // 221184

// mma.sync attention GEMM. Block = (q-tile 128, head, col-half 256), 256 thr.
__global__ __launch_bounds__(256, 1) void k_attn() {
    extern __shared__ char smem[];
    const uint32_t sb = smem_u32(smem);
    const int t = threadIdx.x;
    const int w = t >> 5, l = t & 31;
    const int q0 = blockIdx.x * QT;
    const int n  = blockIdx.y;
    const int chalf = blockIdx.z;
    const int i0 = q0 / HH;
    const int d0 = 44 - i0;

    // stage 51-row score-table slice + k->table-offset index
    float* Stab = (float*)(smem + SM_STAB);
    unsigned short* kidx = (unsigned short*)(smem + SM_KIDX);
    for (int idx = t; idx < 51 * TW; idx += 256) {
        int r = idx / TW, c = idx - r * TW;
        int dxi = r + d0;
        Stab[idx] = (dxi >= 0 && dxi < TW) ? g_S[n * TT + dxi * TW + c] : -1e30f;
    }
    for (int k = t; k < NQ; k += 256)
        kidx[k] = (unsigned short)((k / HH) * TW + (k % HH));
    __syncthreads();

    // producer constants: warp w owns A fragment tile mt=w; lane rows r0, r0+8
    const int r0 = w * 16 + (l >> 2);
    const int r1 = r0 + 8;
    const int qa = q0 + r0, qb = q0 + r1;
    const int qi0 = qa / HH, qj0 = qa - qi0 * HH;
    const int qi1 = qb / HH, qj1 = qb - qi1 * HH;
    const float* Sq0 = Stab + (47 - qi0 - d0) * TW + (47 - qj0);
    const float* Sq1 = Stab + (47 - qi1 - d0) * TW + (47 - qj1);
    const float M20 = g_M[n * NQ + qa];
    const float M21 = g_M[n * NQ + qb];
    float z0 = 0.f, z1 = 0.f;
    const int kbase = (l & 3) * 2;

    // cp.async source bases: thread copies segment seg (one n8-group), 8x16B per op
    const int seg = t >> 3, uu = t & 7;
    const size_t srcSegOff = ((size_t)(chalf * 32 + seg) * 36) * 1024;
    const char* srcH = (const char*)g_Xbh4 + srcSegOff;
    const char* srcL = (const char*)g_Xbl4 + srcSegOff;

    float acc[4][8][4];
    #pragma unroll
    for (int m = 0; m < 4; m++)
        #pragma unroll
        for (int nn = 0; nn < 8; nn++)
            #pragma unroll
            for (int cdx = 0; cdx < 4; cdx++) acc[m][nn][cdx] = 0.f;

    const int wm = w >> 2, wn = w & 3;

    // ---- produce chunk kcp into buffer buf (A via exp, B via cp.async) ----
    auto produce = [&](int kcp, int buf) {
        char* Ah = smem + SM_BUF + buf * BUFSZ;
        char* Al = Ah + OFF_AL;
        #pragma unroll
        for (int ks = 0; ks < 4; ks++) {
            const int k0 = kcp * 64 + ks * 16 + kbase;
            const int i00 = kidx[k0],     i01 = kidx[k0 + 1];
            const int i08 = kidx[k0 + 8], i09 = kidx[k0 + 9];
            float pa0 = fexp2(Sq0[i00] - M20), pa1 = fexp2(Sq0[i01] - M20);
            float pa8 = fexp2(Sq0[i08] - M20), pa9 = fexp2(Sq0[i09] - M20);
            float pb0 = fexp2(Sq1[i00] - M21), pb1 = fexp2(Sq1[i01] - M21);
            float pb8 = fexp2(Sq1[i08] - M21), pb9 = fexp2(Sq1[i09] - M21);
            z0 += pa0 + pa1 + pa8 + pa9;
            z1 += pb0 + pb1 + pb8 + pb9;
            __nv_bfloat162 h0 = __floats2bfloat162_rn(pa0, pa1);
            __nv_bfloat162 h1 = __floats2bfloat162_rn(pb0, pb1);
            __nv_bfloat162 h2 = __floats2bfloat162_rn(pa8, pa9);
            __nv_bfloat162 h3 = __floats2bfloat162_rn(pb8, pb9);
            __nv_bfloat162 e0 = __floats2bfloat162_rn(pa0 - __bfloat162float(h0.x),
                                                      pa1 - __bfloat162float(h0.y));
            __nv_bfloat162 e1 = __floats2bfloat162_rn(pb0 - __bfloat162float(h1.x),
                                                      pb1 - __bfloat162float(h1.y));
            __nv_bfloat162 e2 = __floats2bfloat162_rn(pa8 - __bfloat162float(h2.x),
                                                      pa9 - __bfloat162float(h2.y));
            __nv_bfloat162 e3 = __floats2bfloat162_rn(pb8 - __bfloat162float(h3.x),
                                                      pb9 - __bfloat162float(h3.y));
            const uint32_t off = (uint32_t)(((w * 4 + ks) * 32 + l) * 16);
            *(uint4*)(Ah + off) = make_uint4(*(uint32_t*)&h0, *(uint32_t*)&h1,
                                             *(uint32_t*)&h2, *(uint32_t*)&h3);
            *(uint4*)(Al + off) = make_uint4(*(uint32_t*)&e0, *(uint32_t*)&e1,
                                             *(uint32_t*)&e2, *(uint32_t*)&e3);
        }
        // B: copy this chunk's 1KB fragment block per segment (hi & lo)
        const uint32_t dBh = sb + SM_BUF + buf * BUFSZ + OFF_BH + seg * 1024;
        const uint32_t dBl = sb + SM_BUF + buf * BUFSZ + OFF_BL + seg * 1024;
        const char* sH = srcH + (size_t)kcp * 1024;
        const char* sL = srcL + (size_t)kcp * 1024;
        #pragma unroll
        for (int i = 0; i < 8; i++) {
            int u16 = (uu + i * 8) * 16;
            cpa16(dBh + u16, sH + u16);
            cpa16(dBl + u16, sL + u16);
        }
        asm volatile("cp.async.commit_group;" ::: "memory");
    };

    produce(0, 0);

    for (int kc = 0; kc < NCHUNK; kc++) {
        const int buf = kc & 1;
        if (kc + 1 < NCHUNK) {
            produce(kc + 1, buf ^ 1);
            asm volatile("cp.async.wait_group 1;" ::: "memory");
        } else {
            asm volatile("cp.async.wait_group 0;" ::: "memory");
        }
        __syncthreads();

        const uint4* AhP = (const uint4*)(smem + SM_BUF + buf * BUFSZ);
        const uint4* AlP = (const uint4*)(smem + SM_BUF + buf * BUFSZ + OFF_AL);
        const uint2* BhP = (const uint2*)(smem + SM_BUF + buf * BUFSZ + OFF_BH);
        const uint2* BlP = (const uint2*)(smem + SM_BUF + buf * BUFSZ + OFF_BL);

        #pragma unroll
        for (int ks = 0; ks < 4; ks++) {
            uint4 ah[4];
            #pragma unroll
            for (int m = 0; m < 4; m++)
                ah[m] = AhP[((wm * 4 + m) * 4 + ks) * 32 + l];
            uint2 bh[8];
            #pragma unroll
            for (int nn = 0; nn < 8; nn++)
                bh[nn] = BhP[((wn * 8 + nn) * 4 + ks) * 32 + l];
            #pragma unroll
            for (int m = 0; m < 4; m++)
                #pragma unroll
                for (int nn = 0; nn < 8; nn++)
                    mma16816(acc[m][nn], ah[m], bh[nn]);
            uint2 bl[8];
            #pragma unroll
            for (int nn = 0; nn < 8; nn++)
                bl[nn] = BlP[((wn * 8 + nn) * 4 + ks) * 32 + l];
            #pragma unroll
            for (int m = 0; m < 4; m++)
                #pragma unroll
                for (int nn = 0; nn < 8; nn++)
                    mma16816(acc[m][nn], ah[m], bl[nn]);
            uint4 al[4];
            #pragma unroll
            for (int m = 0; m < 4; m++)
                al[m] = AlP[((wm * 4 + m) * 4 + ks) * 32 + l];
            #pragma unroll
            for (int m = 0; m < 4; m++)
                #pragma unroll
                for (int nn = 0; nn < 8; nn++)
                    mma16816(acc[m][nn], al[m], bh[nn]);
        }
        __syncthreads();
    }

    // Z: rows r0/r1 are each covered by the 4 lanes sharing l>>2 in warp w
    z0 += __shfl_xor_sync(0xFFFFFFFFu, z0, 1);
    z0 += __shfl_xor_sync(0xFFFFFFFFu, z0, 2);
    z1 += __shfl_xor_sync(0xFFFFFFFFu, z1, 1);
    z1 += __shfl_xor_sync(0xFFFFFFFFu, z1, 2);
    float* sZ = (float*)(smem + SM_Z);
    if ((l & 3) == 0) { sZ[r0] = z0; sZ[r1] = z1; }
    __syncthreads();

    // epilogue: scale by 1/Z and store to g_U
    #pragma unroll
    for (int m = 0; m < 4; m++) {
        const int rowa = wm * 64 + m * 16 + (l >> 2);
        const float rza = 1.0f / sZ[rowa];
        const float rzb = 1.0f / sZ[rowa + 8];
        float* dsta = g_U + ((size_t)n * NQ + (q0 + rowa)) * CC;
        float* dstb = dsta + 8 * CC;
        #pragma unroll
        for (int nn = 0; nn < 8; nn++) {
            const int col = chalf * NCOL + wn * 64 + nn * 8 + (l & 3) * 2;
            float2 va = make_float2(acc[m][nn][0] * rza, acc[m][nn][1] * rza);
            float2 vb = make_float2(acc[m][nn][2] * rzb, acc[m][nn][3] * rzb);
            *(float2*)(dsta + col) = va;
            *(float2*)(dstb + col) = vb;
        }
    }
}

// ---------------------------------------------------------------------------
__global__ __launch_bounds__(256) void k_proj(const float* __restrict__ bfc,
                                              float* __restrict__ out) {
    __shared__ float As[128][33];
    __shared__ float Ws[32][64];
    const int t = threadIdx.x;
    const int r0 = blockIdx.x * 128;
    const int b = r0 / NQ;
    const int q0 = r0 - b * NQ;
    const int rg = t >> 3;
    const int r_l = rg * 4;
    const int eo0 = (t & 7) * 8;

    float acc[4][8];
    #pragma unroll
    for (int m = 0; m < 4; m++)
        #pragma unroll
        for (int c = 0; c < 8; c++) acc[m][c] = 0.f;

    for (int fck = 0; fck < CC; fck += 32) {
        __syncthreads();
        {
            int fc = t & 31, rl0 = t >> 5;
            int f = fck + fc;
            int nn = f >> 6, e = f & 63;
            const float* src = g_U + ((size_t)nn * NQ + q0) * CC + b * EE + e;
            #pragma unroll
            for (int s = 0; s < 16; s++)
                As[rl0 + s * 8][fc] = src[(size_t)(rl0 + s * 8) * CC];
        }
        {
            int eo = t & 63, f0 = t >> 6;
            #pragma unroll
            for (int s = 0; s < 8; s++)
                Ws[f0 + s * 4][eo] = g_Wpt[(fck + f0 + s * 4) * EE + eo];
        }
        __syncthreads();
        #pragma unroll 8
        for (int fc = 0; fc < 32; fc++) {
            float a_[4], w_[8];
            #pragma unroll
            for (int m = 0; m < 4; m++) a_[m] = As[r_l + m][fc];
            #pragma unroll
            for (int c = 0; c < 8; c++) w_[c] = Ws[fc][eo0 + c];
            #pragma unroll
            for (int m = 0; m < 4; m++)
                #pragma unroll
                for (int c = 0; c < 8; c++)
                    acc[m][c] = fmaf(a_[m], w_[c], acc[m][c]);
        }
    }
    #pragma unroll
    for (int m = 0; m < 4; m++) {
        int r = r0 + r_l + m;
        #pragma unroll
        for (int c = 0; c < 8; c++)
            out[r * EE + eo0 + c] = acc[m][c] + bfc[eo0 + c];
    }
}

// ---------------------------------------------------------------------------
extern "C" void kernel_launch(void* const* d_in, const int* in_sizes, int n_in,
                              void* d_out, int out_size) {
    const float* hs   = (const float*)d_in[0];
    const float* wsig = (const float*)d_in[3];
    const float* wfc  = (const float*)d_in[5];
    const float* bfc  = (const float*)d_in[6];
    float* out = (float*)d_out;

    cudaFuncSetAttribute(k_attn, cudaFuncAttributeMaxDynamicSharedMemorySize, SMEM_TOTAL);

    k_xsplit<<<(NW32 + 255) / 256, 256>>>(hs);
    k_wpt<<<(CC * EE + 255) / 256, 256>>>(wfc);
    k_table<<<(NHD * TT + 255) / 256, 256>>>(wsig);
    k_colmax<<<(NHD * TW * HH + 255) / 256, 256>>>();
    k_rowmax<<<(NHD * NQ + 255) / 256, 256>>>();

    dim3 ga(NQ / QT, NHD, 2);   // (18, 8, 2)
    k_attn<<<ga, 256, SMEM_TOTAL>>>();

    k_proj<<<(BB * NQ) / 128, 256>>>(bfc, out);
}

// round 7
// speedup vs baseline: 3.9017x; 1.4666x over previous
#include <cuda_runtime.h>
#include <cuda_fp16.h>
#include <cstdint>

#define WW 48
#define HH 48
#define NQ 2304
#define NHD 8
#define EE 64
#define BB 8
#define CC 512
#define TW 95
#define TT (TW*TW)
#define LOG2E 1.4426950408889634f

#define QT 128            // M per block
#define NCOL 256          // N per block
#define KC 64             // K chunk
#define NCHUNK (NQ/KC)    // 36
#define NW32 (CC*NQ/2)    // b32 words in X operand (589824)

// ---- device scratch (no runtime allocation allowed) ----
__device__ float g_S[NHD * TT];
__device__ float g_cm[NHD * TW * HH];
__device__ float g_M[NHD * NQ];
__device__ __align__(256) uint4 g_Xbh4[NW32 / 4];   // X hi fp16, fragment-major
__device__ __align__(256) uint4 g_Xbl4[NW32 / 4];   // X lo fp16, fragment-major
__device__ __align__(16) __half g_Upk[NQ * BB * NHD * EE];  // U fp16: [q][b][n*64+e]
__device__ __align__(16) __half g_Wth[EE * CC];     // W^T hi fp16: [eo][f=n*64+e]
__device__ __align__(16) __half g_Wtl[EE * CC];     // W^T lo

__device__ __forceinline__ float fexp2(float x) {
    float y; asm("ex2.approx.ftz.f32 %0, %1;" : "=f"(y) : "f"(x)); return y;
}
__device__ __forceinline__ uint32_t smem_u32(const void* p) {
    uint32_t a;
    asm("{ .reg .u64 t; cvta.to.shared.u64 t, %1; cvt.u32.u64 %0, t; }" : "=r"(a) : "l"(p));
    return a;
}
__device__ __forceinline__ void cpa16(uint32_t dst, const void* src) {
    asm volatile("cp.async.cg.shared.global [%0], [%1], 16;" :: "r"(dst), "l"(src));
}
__device__ __forceinline__ void mma16816h(float* c, const uint4& a, const uint2& b) {
    asm volatile(
        "mma.sync.aligned.m16n8k16.row.col.f32.f16.f16.f32 "
        "{%0,%1,%2,%3}, {%4,%5,%6,%7}, {%8,%9}, {%0,%1,%2,%3};"
        : "+f"(c[0]), "+f"(c[1]), "+f"(c[2]), "+f"(c[3])
        : "r"(a.x), "r"(a.y), "r"(a.z), "r"(a.w), "r"(b.x), "r"(b.y));
}

// ---------------------------------------------------------------------------
// Split X into fp16 hi/lo, fragment-major (same index map as R6, validated):
// o: [g 64][kc 36][ks 4][lane 32][word 2]
__global__ void k_xsplit(const float* __restrict__ hs) {
    int o = blockIdx.x * blockDim.x + threadIdx.x;
    if (o >= NW32) return;
    int word = o & 1;
    int lane = (o >> 1) & 31;
    int ks   = (o >> 6) & 3;
    int rem  = o >> 8;
    int kc   = rem % 36;
    int g    = rem / 36;
    int n8   = lane >> 2;
    int kk0  = word * 8 + (lane & 3) * 2;
    int c    = g * 8 + n8;
    int b    = c >> 6, e = c & 63;
    int k    = kc * 64 + ks * 16 + kk0;
    float x0 = hs[(b * NQ + k) * EE + e];
    float x1 = hs[(b * NQ + k + 1) * EE + e];
    __half2 h  = __floats2half2_rn(x0, x1);
    __half2 lo = __floats2half2_rn(x0 - __half2float(__low2half(h)),
                                   x1 - __half2float(__high2half(h)));
    ((uint32_t*)g_Xbh4)[o] = *(uint32_t*)&h;
    ((uint32_t*)g_Xbl4)[o] = *(uint32_t*)&lo;
}

// W^T split: Wt[eo][f=n*64+e] = wfc[eo][e*8+n], fp16 hi/lo
__global__ void k_wsplit(const float* __restrict__ wfc) {
    int o = blockIdx.x * blockDim.x + threadIdx.x;
    if (o >= EE * CC) return;
    int eo = o >> 9, f = o & 511;
    int n = f >> 6, e = f & 63;
    float v = wfc[eo * CC + e * NHD + n];
    __half h = __float2half(v);
    g_Wth[o] = h;
    g_Wtl[o] = __float2half(v - __half2float(h));
}

__global__ void k_table(const float* __restrict__ wsig) {
    int o = blockIdx.x * blockDim.x + threadIdx.x;
    if (o >= NHD * TT) return;
    int n = o / TT, r = o - n * TT;
    int dxi = r / TW, dyi = r - dxi * TW;
    float dx = (float)(dxi - 47), dy = (float)(dyi - 47);
    const float* w = wsig + n * 5;
    g_S[o] = (w[0]*dx + w[1]*dy + w[2]*dx*dx + w[3]*dy*dy + w[4]*dx*dy) * LOG2E;
}

__global__ void k_colmax() {
    int o = blockIdx.x * blockDim.x + threadIdx.x;
    if (o >= NHD * TW * HH) return;
    int n = o / (TW * HH), r = o - n * TW * HH;
    int dxi = r / HH, j = r - dxi * HH;
    const float* row = g_S + n * TT + dxi * TW + (47 - j);
    float m = -1e30f;
    #pragma unroll 8
    for (int l = 0; l < HH; l++) m = fmaxf(m, row[l]);
    g_cm[o] = m;
}

__global__ void k_rowmax() {
    int o = blockIdx.x * blockDim.x + threadIdx.x;
    if (o >= NHD * NQ) return;
    int n = o / NQ, r = o - n * NQ;
    int i = r / HH, j = r - i * HH;
    float m = -1e30f;
    #pragma unroll 8
    for (int k = 0; k < WW; k++)
        m = fmaxf(m, g_cm[(n * TW + (k - i + 47)) * HH + j]);
    g_M[o] = m;
}

// ---------------------------------------------------------------------------
// Dynamic smem layout (bytes)
#define SM_STAB 0                 // 51*95*4 = 19380
#define SM_KIDX 19392             // 2304*2  = 4608
#define SM_Z    24000             // 128*4
#define SM_BUF  24576
#define BUFSZ   81920             // Ah 16K | Bh 32K | Bl 32K
#define OFF_BH  16384
#define OFF_BL  49152
#define SMEM_TOTAL (SM_BUF + 2 * BUFSZ)   // 188416

// mma.sync fp16 attention GEMM. Block = (q-tile 128, head, col-half 256).
__global__ __launch_bounds__(256, 1) void k_attn() {
    extern __shared__ char smem[];
    const uint32_t sb = smem_u32(smem);
    const int t = threadIdx.x;
    const int w = t >> 5, l = t & 31;
    const int q0 = blockIdx.x * QT;
    const int n  = blockIdx.y;
    const int chalf = blockIdx.z;
    const int i0 = q0 / HH;
    const int d0 = 44 - i0;

    float* Stab = (float*)(smem + SM_STAB);
    unsigned short* kidx = (unsigned short*)(smem + SM_KIDX);
    for (int idx = t; idx < 51 * TW; idx += 256) {
        int r = idx / TW, c = idx - r * TW;
        int dxi = r + d0;
        Stab[idx] = (dxi >= 0 && dxi < TW) ? g_S[n * TT + dxi * TW + c] : -1e30f;
    }
    for (int k = t; k < NQ; k += 256)
        kidx[k] = (unsigned short)((k / HH) * TW + (k % HH));
    __syncthreads();

    const int r0 = w * 16 + (l >> 2);
    const int r1 = r0 + 8;
    const int qa = q0 + r0, qb = q0 + r1;
    const int qi0 = qa / HH, qj0 = qa - qi0 * HH;
    const int qi1 = qb / HH, qj1 = qb - qi1 * HH;
    const float* Sq0 = Stab + (47 - qi0 - d0) * TW + (47 - qj0);
    const float* Sq1 = Stab + (47 - qi1 - d0) * TW + (47 - qj1);
    const float M20 = g_M[n * NQ + qa];
    const float M21 = g_M[n * NQ + qb];
    float z0 = 0.f, z1 = 0.f;
    const int kbase = (l & 3) * 2;

    const int seg = t >> 3, uu = t & 7;
    const size_t srcSegOff = ((size_t)(chalf * 32 + seg) * 36) * 1024;
    const char* srcH = (const char*)g_Xbh4 + srcSegOff;
    const char* srcL = (const char*)g_Xbl4 + srcSegOff;

    float acc[4][8][4];
    #pragma unroll
    for (int m = 0; m < 4; m++)
        #pragma unroll
        for (int nn = 0; nn < 8; nn++)
            #pragma unroll
            for (int cdx = 0; cdx < 4; cdx++) acc[m][nn][cdx] = 0.f;

    const int wm = w >> 2, wn = w & 3;

    auto produce = [&](int kcp, int buf) {
        char* Ah = smem + SM_BUF + buf * BUFSZ;
        #pragma unroll
        for (int ks = 0; ks < 4; ks++) {
            const int k0 = kcp * 64 + ks * 16 + kbase;
            const int i00 = kidx[k0],     i01 = kidx[k0 + 1];
            const int i08 = kidx[k0 + 8], i09 = kidx[k0 + 9];
            float pa0 = fexp2(Sq0[i00] - M20), pa1 = fexp2(Sq0[i01] - M20);
            float pa8 = fexp2(Sq0[i08] - M20), pa9 = fexp2(Sq0[i09] - M20);
            float pb0 = fexp2(Sq1[i00] - M21), pb1 = fexp2(Sq1[i01] - M21);
            float pb8 = fexp2(Sq1[i08] - M21), pb9 = fexp2(Sq1[i09] - M21);
            z0 += pa0 + pa1 + pa8 + pa9;
            z1 += pb0 + pb1 + pb8 + pb9;
            __half2 h0 = __floats2half2_rn(pa0, pa1);   // a0: row r0, k0/k0+1
            __half2 h1 = __floats2half2_rn(pb0, pb1);   // a1: row r1
            __half2 h2 = __floats2half2_rn(pa8, pa9);   // a2: row r0, k+8
            __half2 h3 = __floats2half2_rn(pb8, pb9);   // a3: row r1, k+8
            const uint32_t off = (uint32_t)(((w * 4 + ks) * 32 + l) * 16);
            *(uint4*)(Ah + off) = make_uint4(*(uint32_t*)&h0, *(uint32_t*)&h1,
                                             *(uint32_t*)&h2, *(uint32_t*)&h3);
        }
        const uint32_t dBh = sb + SM_BUF + buf * BUFSZ + OFF_BH + seg * 1024;
        const uint32_t dBl = sb + SM_BUF + buf * BUFSZ + OFF_BL + seg * 1024;
        const char* sH = srcH + (size_t)kcp * 1024;
        const char* sL = srcL + (size_t)kcp * 1024;
        #pragma unroll
        for (int i = 0; i < 8; i++) {
            int u16 = (uu + i * 8) * 16;
            cpa16(dBh + u16, sH + u16);
            cpa16(dBl + u16, sL + u16);
        }
        asm volatile("cp.async.commit_group;" ::: "memory");
    };

    produce(0, 0);

    for (int kc = 0; kc < NCHUNK; kc++) {
        const int buf = kc & 1;
        if (kc + 1 < NCHUNK) {
            produce(kc + 1, buf ^ 1);
            asm volatile("cp.async.wait_group 1;" ::: "memory");
        } else {
            asm volatile("cp.async.wait_group 0;" ::: "memory");
        }
        __syncthreads();

        const uint4* AhP = (const uint4*)(smem + SM_BUF + buf * BUFSZ);
        const uint2* BhP = (const uint2*)(smem + SM_BUF + buf * BUFSZ + OFF_BH);
        const uint2* BlP = (const uint2*)(smem + SM_BUF + buf * BUFSZ + OFF_BL);

        #pragma unroll
        for (int ks = 0; ks < 4; ks++) {
            uint4 ah[4];
            #pragma unroll
            for (int m = 0; m < 4; m++)
                ah[m] = AhP[((wm * 4 + m) * 4 + ks) * 32 + l];
            uint2 bh[8];
            #pragma unroll
            for (int nn = 0; nn < 8; nn++)
                bh[nn] = BhP[((wn * 8 + nn) * 4 + ks) * 32 + l];
            #pragma unroll
            for (int m = 0; m < 4; m++)
                #pragma unroll
                for (int nn = 0; nn < 8; nn++)
                    mma16816h(acc[m][nn], ah[m], bh[nn]);
            uint2 bl[8];
            #pragma unroll
            for (int nn = 0; nn < 8; nn++)
                bl[nn] = BlP[((wn * 8 + nn) * 4 + ks) * 32 + l];
            #pragma unroll
            for (int m = 0; m < 4; m++)
                #pragma unroll
                for (int nn = 0; nn < 8; nn++)
                    mma16816h(acc[m][nn], ah[m], bl[nn]);
        }
        __syncthreads();
    }

    z0 += __shfl_xor_sync(0xFFFFFFFFu, z0, 1);
    z0 += __shfl_xor_sync(0xFFFFFFFFu, z0, 2);
    z1 += __shfl_xor_sync(0xFFFFFFFFu, z1, 1);
    z1 += __shfl_xor_sync(0xFFFFFFFFu, z1, 2);
    float* sZ = (float*)(smem + SM_Z);
    if ((l & 3) == 0) { sZ[r0] = z0; sZ[r1] = z1; }
    __syncthreads();

    // epilogue: scale by 1/Z, store fp16 to g_Upk[q][b][n*64+e]
    const int bcol = chalf * 4 + wn;          // batch index this warp writes
    #pragma unroll
    for (int m = 0; m < 4; m++) {
        const int rowa = wm * 64 + m * 16 + (l >> 2);
        const float rza = 1.0f / sZ[rowa];
        const float rzb = 1.0f / sZ[rowa + 8];
        __half* dsta = g_Upk + (size_t)(q0 + rowa) * (BB * NHD * EE) + bcol * (NHD * EE) + n * EE;
        __half* dstb = dsta + (size_t)8 * (BB * NHD * EE);
        #pragma unroll
        for (int nn = 0; nn < 8; nn++) {
            const int e = nn * 8 + (l & 3) * 2;
            __half2 va = __floats2half2_rn(acc[m][nn][0] * rza, acc[m][nn][1] * rza);
            __half2 vb = __floats2half2_rn(acc[m][nn][2] * rzb, acc[m][nn][3] * rzb);
            *(__half2*)(dsta + e) = va;
            *(__half2*)(dstb + e) = vb;
        }
    }
}

// ---------------------------------------------------------------------------
// Final projection via fp16 mma: out[b,q,eo] = b_fc[eo] + sum_f U[q][b][f]*Wt[eo][f]
// Block: 128 rows (q) x 64 eo, K=512 in 8 chunks. Grid (18, 8=b).
__global__ __launch_bounds__(256) void k_proj(const float* __restrict__ bfc,
                                              float* __restrict__ out) {
    __shared__ __half As[128][72];
    __shared__ __half Whs[64][72];
    __shared__ __half Wls[64][72];
    const int t = threadIdx.x;
    const int w = t >> 5, l = t & 31;
    const int q0 = blockIdx.x * 128;
    const int b  = blockIdx.y;
    const int wm = w >> 1, wn = w & 1;

    float acc[2][4][4];
    #pragma unroll
    for (int m = 0; m < 2; m++)
        #pragma unroll
        for (int nt = 0; nt < 4; nt++)
            #pragma unroll
            for (int c = 0; c < 4; c++) acc[m][nt][c] = 0.f;

    for (int fck = 0; fck < 8; fck++) {
        __syncthreads();
        // load A chunk: 128 rows x 64 f fp16 (1024 uint4)
        #pragma unroll
        for (int i = 0; i < 4; i++) {
            int idx = t * 4 + i;
            int row = idx >> 3, u = idx & 7;
            uint4 v = *(const uint4*)(g_Upk + (size_t)(q0 + row) * 4096 + b * 512 + fck * 64 + u * 8);
            *(uint4*)(&As[row][u * 8]) = v;
        }
        // load W chunks: 64 x 64 each (512 uint4 each)
        #pragma unroll
        for (int i = 0; i < 2; i++) {
            int idx = t * 2 + i;
            int eo = idx >> 3, u = idx & 7;
            uint4 vh = *(const uint4*)(g_Wth + eo * 512 + fck * 64 + u * 8);
            uint4 vl = *(const uint4*)(g_Wtl + eo * 512 + fck * 64 + u * 8);
            *(uint4*)(&Whs[eo][u * 8]) = vh;
            *(uint4*)(&Wls[eo][u * 8]) = vl;
        }
        __syncthreads();

        #pragma unroll
        for (int ks = 0; ks < 4; ks++) {
            const int kb = ks * 16;
            uint4 a[2];
            #pragma unroll
            for (int m = 0; m < 2; m++) {
                const int row = wm * 32 + m * 16 + (l >> 2);
                a[m].x = *(const uint32_t*)(&As[row][kb + (l & 3) * 2]);
                a[m].y = *(const uint32_t*)(&As[row + 8][kb + (l & 3) * 2]);
                a[m].z = *(const uint32_t*)(&As[row][kb + 8 + (l & 3) * 2]);
                a[m].w = *(const uint32_t*)(&As[row + 8][kb + 8 + (l & 3) * 2]);
            }
            #pragma unroll
            for (int nt = 0; nt < 4; nt++) {
                const int eo = wn * 32 + nt * 8 + (l >> 2);
                uint2 bh, bl;
                bh.x = *(const uint32_t*)(&Whs[eo][kb + (l & 3) * 2]);
                bh.y = *(const uint32_t*)(&Whs[eo][kb + 8 + (l & 3) * 2]);
                bl.x = *(const uint32_t*)(&Wls[eo][kb + (l & 3) * 2]);
                bl.y = *(const uint32_t*)(&Wls[eo][kb + 8 + (l & 3) * 2]);
                #pragma unroll
                for (int m = 0; m < 2; m++) {
                    mma16816h(acc[m][nt], a[m], bh);
                    mma16816h(acc[m][nt], a[m], bl);
                }
            }
        }
    }

    // epilogue
    #pragma unroll
    for (int m = 0; m < 2; m++) {
        const int row = wm * 32 + m * 16 + (l >> 2);
        #pragma unroll
        for (int nt = 0; nt < 4; nt++) {
            const int eo = wn * 32 + nt * 8 + (l & 3) * 2;
            float2 v0 = make_float2(acc[m][nt][0] + bfc[eo], acc[m][nt][1] + bfc[eo + 1]);
            float2 v1 = make_float2(acc[m][nt][2] + bfc[eo], acc[m][nt][3] + bfc[eo + 1]);
            *(float2*)(out + (size_t)(b * NQ + q0 + row) * EE + eo) = v0;
            *(float2*)(out + (size_t)(b * NQ + q0 + row + 8) * EE + eo) = v1;
        }
    }
}

// ---------------------------------------------------------------------------
extern "C" void kernel_launch(void* const* d_in, const int* in_sizes, int n_in,
                              void* d_out, int out_size) {
    const float* hs   = (const float*)d_in[0];
    const float* wsig = (const float*)d_in[3];
    const float* wfc  = (const float*)d_in[5];
    const float* bfc  = (const float*)d_in[6];
    float* out = (float*)d_out;

    cudaFuncSetAttribute(k_attn, cudaFuncAttributeMaxDynamicSharedMemorySize, SMEM_TOTAL);

    k_xsplit<<<(NW32 + 255) / 256, 256>>>(hs);
    k_wsplit<<<(EE * CC + 255) / 256, 256>>>(wfc);
    k_table<<<(NHD * TT + 255) / 256, 256>>>(wsig);
    k_colmax<<<(NHD * TW * HH + 255) / 256, 256>>>();
    k_rowmax<<<(NHD * NQ + 255) / 256, 256>>>();

    dim3 ga(NQ / QT, NHD, 2);   // (18, 8, 2)
    k_attn<<<ga, 256, SMEM_TOTAL>>>();

    dim3 gp(NQ / 128, BB);      // (18, 8)
    k_proj<<<gp, 256>>>(bfc, out);
}

// round 9
// speedup vs baseline: 5.8131x; 1.4899x over previous
#include <cuda_runtime.h>
#include <cuda_fp16.h>
#include <cstdint>

#define WW 48
#define HH 48
#define NQ 2304
#define NHD 8
#define EE 64
#define BB 8
#define CC 512
#define TW 95
#define TT (TW*TW)
#define LOG2E 1.4426950408889634f

#define QT 128            // M per block
#define NCOL 256          // N per block
#define KC 64             // K chunk
#define NCHUNK (NQ/KC)    // 36
#define NW32 (CC*NQ/2)    // b32 words in X operand (589824)

// ---- device scratch (no runtime allocation allowed) ----
__device__ float g_S[NHD * TT];
__device__ float g_cm[NHD * TW * HH];
__device__ float g_M[NHD * NQ];
__device__ __align__(256) uint4 g_Xbh4[NW32 / 4];   // X fp16, fragment-major
__device__ __align__(16) __half g_Upk[NQ * BB * NHD * EE];  // U fp16: [q][b][n*64+e]
__device__ __align__(16) __half g_Wth[EE * CC];     // W^T hi fp16: [eo][f=n*64+e]
__device__ __align__(16) __half g_Wtl[EE * CC];     // W^T lo

__device__ __forceinline__ float fexp2(float x) {
    float y; asm("ex2.approx.ftz.f32 %0, %1;" : "=f"(y) : "f"(x)); return y;
}
__device__ __forceinline__ uint32_t smem_u32(const void* p) {
    uint32_t a;
    asm("{ .reg .u64 t; cvta.to.shared.u64 t, %1; cvt.u32.u64 %0, t; }" : "=r"(a) : "l"(p));
    return a;
}
__device__ __forceinline__ void cpa16(uint32_t dst, const void* src) {
    asm volatile("cp.async.cg.shared.global [%0], [%1], 16;" :: "r"(dst), "l"(src));
}
__device__ __forceinline__ void mma16816h(float* c, const uint4& a, const uint2& b) {
    asm volatile(
        "mma.sync.aligned.m16n8k16.row.col.f32.f16.f16.f32 "
        "{%0,%1,%2,%3}, {%4,%5,%6,%7}, {%8,%9}, {%0,%1,%2,%3};"
        : "+f"(c[0]), "+f"(c[1]), "+f"(c[2]), "+f"(c[3])
        : "r"(a.x), "r"(a.y), "r"(a.z), "r"(a.w), "r"(b.x), "r"(b.y));
}

// ---------------------------------------------------------------------------
// X -> fp16, fragment-major (index map validated R6/R7):
// o: [g 64][kc 36][ks 4][lane 32][word 2]
__global__ void k_xsplit(const float* __restrict__ hs) {
    int o = blockIdx.x * blockDim.x + threadIdx.x;
    if (o >= NW32) return;
    int word = o & 1;
    int lane = (o >> 1) & 31;
    int ks   = (o >> 6) & 3;
    int rem  = o >> 8;
    int kc   = rem % 36;
    int g    = rem / 36;
    int n8   = lane >> 2;
    int kk0  = word * 8 + (lane & 3) * 2;
    int c    = g * 8 + n8;
    int b    = c >> 6, e = c & 63;
    int k    = kc * 64 + ks * 16 + kk0;
    float x0 = hs[(b * NQ + k) * EE + e];
    float x1 = hs[(b * NQ + k + 1) * EE + e];
    __half2 h = __floats2half2_rn(x0, x1);
    ((uint32_t*)g_Xbh4)[o] = *(uint32_t*)&h;
}

// W^T split: Wt[eo][f=n*64+e] = wfc[eo][e*8+n], fp16 hi/lo
__global__ void k_wsplit(const float* __restrict__ wfc) {
    int o = blockIdx.x * blockDim.x + threadIdx.x;
    if (o >= EE * CC) return;
    int eo = o >> 9, f = o & 511;
    int n = f >> 6, e = f & 63;
    float v = wfc[eo * CC + e * NHD + n];
    __half h = __float2half(v);
    g_Wth[o] = h;
    g_Wtl[o] = __float2half(v - __half2float(h));
}

__global__ void k_table(const float* __restrict__ wsig) {
    int o = blockIdx.x * blockDim.x + threadIdx.x;
    if (o >= NHD * TT) return;
    int n = o / TT, r = o - n * TT;
    int dxi = r / TW, dyi = r - dxi * TW;
    float dx = (float)(dxi - 47), dy = (float)(dyi - 47);
    const float* w = wsig + n * 5;
    g_S[o] = (w[0]*dx + w[1]*dy + w[2]*dx*dx + w[3]*dy*dy + w[4]*dx*dy) * LOG2E;
}

__global__ void k_colmax() {
    int o = blockIdx.x * blockDim.x + threadIdx.x;
    if (o >= NHD * TW * HH) return;
    int n = o / (TW * HH), r = o - n * TW * HH;
    int dxi = r / HH, j = r - dxi * HH;
    const float* row = g_S + n * TT + dxi * TW + (47 - j);
    float m = -1e30f;
    #pragma unroll 8
    for (int l = 0; l < HH; l++) m = fmaxf(m, row[l]);
    g_cm[o] = m;
}

__global__ void k_rowmax() {
    int o = blockIdx.x * blockDim.x + threadIdx.x;
    if (o >= NHD * NQ) return;
    int n = o / NQ, r = o - n * NQ;
    int i = r / HH, j = r - i * HH;
    float m = -1e30f;
    #pragma unroll 8
    for (int k = 0; k < WW; k++)
        m = fmaxf(m, g_cm[(n * TW + (k - i + 47)) * HH + j]);
    g_M[o] = m;
}

// ---------------------------------------------------------------------------
// Dynamic smem layout (bytes)
#define SM_STAB 0                 // 51*95*4 = 19380
#define SM_KIDX 19392             // 2304*2  = 4608
#define SM_Z    24000             // 128*4
#define SM_BUF  24576
#define BUFSZ   49152             // Ah 16K | Bh 32K
#define OFF_BH  16384
#define SMEM_TOTAL (SM_BUF + 2 * BUFSZ)   // 122880

// mma.sync fp16 attention GEMM. Block = (q-tile 128, head, col-half 256).
__global__ __launch_bounds__(256, 1) void k_attn() {
    extern __shared__ char smem[];
    const uint32_t sb = smem_u32(smem);
    const int t = threadIdx.x;
    const int w = t >> 5, l = t & 31;
    const int q0 = blockIdx.x * QT;
    const int n  = blockIdx.y;
    const int chalf = blockIdx.z;
    const int i0 = q0 / HH;
    const int d0 = 44 - i0;

    float* Stab = (float*)(smem + SM_STAB);
    unsigned short* kidx = (unsigned short*)(smem + SM_KIDX);
    for (int idx = t; idx < 51 * TW; idx += 256) {
        int r = idx / TW, c = idx - r * TW;
        int dxi = r + d0;
        Stab[idx] = (dxi >= 0 && dxi < TW) ? g_S[n * TT + dxi * TW + c] : -1e30f;
    }
    for (int k = t; k < NQ; k += 256)
        kidx[k] = (unsigned short)((k / HH) * TW + (k % HH));
    __syncthreads();

    const int r0 = w * 16 + (l >> 2);
    const int r1 = r0 + 8;
    const int qa = q0 + r0, qb = q0 + r1;
    const int qi0 = qa / HH, qj0 = qa - qi0 * HH;
    const int qi1 = qb / HH, qj1 = qb - qi1 * HH;
    const float* Sq0 = Stab + (47 - qi0 - d0) * TW + (47 - qj0);
    const float* Sq1 = Stab + (47 - qi1 - d0) * TW + (47 - qj1);
    const float M20 = g_M[n * NQ + qa];
    const float M21 = g_M[n * NQ + qb];
    float z0 = 0.f, z1 = 0.f;
    const int kbase = (l & 3) * 2;

    const int seg = t >> 3, uu = t & 7;
    const size_t srcSegOff = ((size_t)(chalf * 32 + seg) * 36) * 1024;
    const char* srcH = (const char*)g_Xbh4 + srcSegOff;

    float acc[4][8][4];
    #pragma unroll
    for (int m = 0; m < 4; m++)
        #pragma unroll
        for (int nn = 0; nn < 8; nn++)
            #pragma unroll
            for (int cdx = 0; cdx < 4; cdx++) acc[m][nn][cdx] = 0.f;

    const int wm = w >> 2, wn = w & 3;

    auto produce = [&](int kcp, int buf) {
        char* Ah = smem + SM_BUF + buf * BUFSZ;
        #pragma unroll
        for (int ks = 0; ks < 4; ks++) {
            const int k0 = kcp * 64 + ks * 16 + kbase;
            const int i00 = kidx[k0],     i01 = kidx[k0 + 1];
            const int i08 = kidx[k0 + 8], i09 = kidx[k0 + 9];
            float pa0 = fexp2(Sq0[i00] - M20), pa1 = fexp2(Sq0[i01] - M20);
            float pa8 = fexp2(Sq0[i08] - M20), pa9 = fexp2(Sq0[i09] - M20);
            float pb0 = fexp2(Sq1[i00] - M21), pb1 = fexp2(Sq1[i01] - M21);
            float pb8 = fexp2(Sq1[i08] - M21), pb9 = fexp2(Sq1[i09] - M21);
            z0 += pa0 + pa1 + pa8 + pa9;
            z1 += pb0 + pb1 + pb8 + pb9;
            __half2 h0 = __floats2half2_rn(pa0, pa1);   // row r0, k0/k0+1
            __half2 h1 = __floats2half2_rn(pb0, pb1);   // row r1
            __half2 h2 = __floats2half2_rn(pa8, pa9);   // row r0, k+8
            __half2 h3 = __floats2half2_rn(pb8, pb9);   // row r1, k+8
            const uint32_t off = (uint32_t)(((w * 4 + ks) * 32 + l) * 16);
            *(uint4*)(Ah + off) = make_uint4(*(uint32_t*)&h0, *(uint32_t*)&h1,
                                             *(uint32_t*)&h2, *(uint32_t*)&h3);
        }
        const uint32_t dBh = sb + SM_BUF + buf * BUFSZ + OFF_BH + seg * 1024;
        const char* sH = srcH + (size_t)kcp * 1024;
        #pragma unroll
        for (int i = 0; i < 8; i++) {
            int u16 = (uu + i * 8) * 16;
            cpa16(dBh + u16, sH + u16);
        }
        asm volatile("cp.async.commit_group;" ::: "memory");
    };

    produce(0, 0);

    for (int kc = 0; kc < NCHUNK; kc++) {
        const int buf = kc & 1;
        if (kc + 1 < NCHUNK) {
            produce(kc + 1, buf ^ 1);
            asm volatile("cp.async.wait_group 1;" ::: "memory");
        } else {
            asm volatile("cp.async.wait_group 0;" ::: "memory");
        }
        __syncthreads();

        const uint4* AhP = (const uint4*)(smem + SM_BUF + buf * BUFSZ);
        const uint2* BhP = (const uint2*)(smem + SM_BUF + buf * BUFSZ + OFF_BH);

        #pragma unroll
        for (int ks = 0; ks < 4; ks++) {
            uint4 ah[4];
            #pragma unroll
            for (int m = 0; m < 4; m++)
                ah[m] = AhP[((wm * 4 + m) * 4 + ks) * 32 + l];
            uint2 bh[8];
            #pragma unroll
            for (int nn = 0; nn < 8; nn++)
                bh[nn] = BhP[((wn * 8 + nn) * 4 + ks) * 32 + l];
            #pragma unroll
            for (int m = 0; m < 4; m++)
                #pragma unroll
                for (int nn = 0; nn < 8; nn++)
                    mma16816h(acc[m][nn], ah[m], bh[nn]);
        }
        __syncthreads();
    }

    z0 += __shfl_xor_sync(0xFFFFFFFFu, z0, 1);
    z0 += __shfl_xor_sync(0xFFFFFFFFu, z0, 2);
    z1 += __shfl_xor_sync(0xFFFFFFFFu, z1, 1);
    z1 += __shfl_xor_sync(0xFFFFFFFFu, z1, 2);
    float* sZ = (float*)(smem + SM_Z);
    if ((l & 3) == 0) { sZ[r0] = z0; sZ[r1] = z1; }
    __syncthreads();

    // epilogue: scale by 1/Z, store fp16 to g_Upk[q][b][n*64+e]
    const int bcol = chalf * 4 + wn;          // batch index this warp writes
    #pragma unroll
    for (int m = 0; m < 4; m++) {
        const int rowa = wm * 64 + m * 16 + (l >> 2);
        const float rza = 1.0f / sZ[rowa];
        const float rzb = 1.0f / sZ[rowa + 8];
        __half* dsta = g_Upk + (size_t)(q0 + rowa) * (BB * NHD * EE) + bcol * (NHD * EE) + n * EE;
        __half* dstb = dsta + (size_t)8 * (BB * NHD * EE);
        #pragma unroll
        for (int nn = 0; nn < 8; nn++) {
            const int e = nn * 8 + (l & 3) * 2;
            __half2 va = __floats2half2_rn(acc[m][nn][0] * rza, acc[m][nn][1] * rza);
            __half2 vb = __floats2half2_rn(acc[m][nn][2] * rzb, acc[m][nn][3] * rzb);
            *(__half2*)(dsta + e) = va;
            *(__half2*)(dstb + e) = vb;
        }
    }
}

// ---------------------------------------------------------------------------
// Final projection via fp16 mma: out[b,q,eo] = b_fc[eo] + sum_f U[q][b][f]*Wt[eo][f]
// Block: 128 rows (q) x 64 eo, K=512 in 8 chunks. Grid (18, 8=b).
__global__ __launch_bounds__(256) void k_proj(const float* __restrict__ bfc,
                                              float* __restrict__ out) {
    __shared__ __half As[128][72];
    __shared__ __half Whs[64][72];
    __shared__ __half Wls[64][72];
    const int t = threadIdx.x;
    const int w = t >> 5, l = t & 31;
    const int q0 = blockIdx.x * 128;
    const int b  = blockIdx.y;
    const int wm = w >> 1, wn = w & 1;

    float acc[2][4][4];
    #pragma unroll
    for (int m = 0; m < 2; m++)
        #pragma unroll
        for (int nt = 0; nt < 4; nt++)
            #pragma unroll
            for (int c = 0; c < 4; c++) acc[m][nt][c] = 0.f;

    for (int fck = 0; fck < 8; fck++) {
        __syncthreads();
        #pragma unroll
        for (int i = 0; i < 4; i++) {
            int idx = t * 4 + i;
            int row = idx >> 3, u = idx & 7;
            uint4 v = *(const uint4*)(g_Upk + (size_t)(q0 + row) * 4096 + b * 512 + fck * 64 + u * 8);
            *(uint4*)(&As[row][u * 8]) = v;
        }
        #pragma unroll
        for (int i = 0; i < 2; i++) {
            int idx = t * 2 + i;
            int eo = idx >> 3, u = idx & 7;
            uint4 vh = *(const uint4*)(g_Wth + eo * 512 + fck * 64 + u * 8);
            uint4 vl = *(const uint4*)(g_Wtl + eo * 512 + fck * 64 + u * 8);
            *(uint4*)(&Whs[eo][u * 8]) = vh;
            *(uint4*)(&Wls[eo][u * 8]) = vl;
        }
        __syncthreads();

        #pragma unroll
        for (int ks = 0; ks < 4; ks++) {
            const int kb = ks * 16;
            uint4 a[2];
            #pragma unroll
            for (int m = 0; m < 2; m++) {
                const int row = wm * 32 + m * 16 + (l >> 2);
                a[m].x = *(const uint32_t*)(&As[row][kb + (l & 3) * 2]);
                a[m].y = *(const uint32_t*)(&As[row + 8][kb + (l & 3) * 2]);
                a[m].z = *(const uint32_t*)(&As[row][kb + 8 + (l & 3) * 2]);
                a[m].w = *(const uint32_t*)(&As[row + 8][kb + 8 + (l & 3) * 2]);
            }
            #pragma unroll
            for (int nt = 0; nt < 4; nt++) {
                const int eo = wn * 32 + nt * 8 + (l >> 2);
                uint2 bh, bl;
                bh.x = *(const uint32_t*)(&Whs[eo][kb + (l & 3) * 2]);
                bh.y = *(const uint32_t*)(&Whs[eo][kb + 8 + (l & 3) * 2]);
                bl.x = *(const uint32_t*)(&Wls[eo][kb + (l & 3) * 2]);
                bl.y = *(const uint32_t*)(&Wls[eo][kb + 8 + (l & 3) * 2]);
                #pragma unroll
                for (int m = 0; m < 2; m++) {
                    mma16816h(acc[m][nt], a[m], bh);
                    mma16816h(acc[m][nt], a[m], bl);
                }
            }
        }
    }

    #pragma unroll
    for (int m = 0; m < 2; m++) {
        const int row = wm * 32 + m * 16 + (l >> 2);
        #pragma unroll
        for (int nt = 0; nt < 4; nt++) {
            const int eo = wn * 32 + nt * 8 + (l & 3) * 2;
            float2 v0 = make_float2(acc[m][nt][0] + bfc[eo], acc[m][nt][1] + bfc[eo + 1]);
            float2 v1 = make_float2(acc[m][nt][2] + bfc[eo], acc[m][nt][3] + bfc[eo + 1]);
            *(float2*)(out + (size_t)(b * NQ + q0 + row) * EE + eo) = v0;
            *(float2*)(out + (size_t)(b * NQ + q0 + row + 8) * EE + eo) = v1;
        }
    }
}

// ---------------------------------------------------------------------------
extern "C" void kernel_launch(void* const* d_in, const int* in_sizes, int n_in,
                              void* d_out, int out_size) {
    const float* hs   = (const float*)d_in[0];
    const float* wsig = (const float*)d_in[3];
    const float* wfc  = (const float*)d_in[5];
    const float* bfc  = (const float*)d_in[6];
    float* out = (float*)d_out;

    cudaFuncSetAttribute(k_attn, cudaFuncAttributeMaxDynamicSharedMemorySize, SMEM_TOTAL);

    k_xsplit<<<(NW32 + 255) / 256, 256>>>(hs);
    k_wsplit<<<(EE * CC + 255) / 256, 256>>>(wfc);
    k_table<<<(NHD * TT + 255) / 256, 256>>>(wsig);
    k_colmax<<<(NHD * TW * HH + 255) / 256, 256>>>();
    k_rowmax<<<(NHD * NQ + 255) / 256, 256>>>();

    dim3 ga(NQ / QT, NHD, 2);   // (18, 8, 2)
    k_attn<<<ga, 256, SMEM_TOTAL>>>();

    dim3 gp(NQ / 128, BB);      // (18, 8)
    k_proj<<<gp, 256>>>(bfc, out);
}

// round 10
// speedup vs baseline: 7.0405x; 1.2111x over previous
#include <cuda_runtime.h>
#include <cuda_fp16.h>
#include <cstdint>

#define WW 48
#define HH 48
#define NQ 2304
#define NHD 8
#define EE 64
#define BB 8
#define CC 512
#define TW 95
#define TT (TW*TW)
#define LOG2E 1.4426950408889634f

#define QT 128            // M per block
#define NCOL 256          // N per block
#define KC 48             // K chunk = one key row kx
#define NCHUNK 48
#define NW32 (CC*NQ/2)    // b32 words in X operand (589824)
#define NWW (EE*CC)       // wsplit items (32768)

// ---- device scratch ----
__device__ float g_S[NHD * TT];
__device__ float g_cm[NHD * TW * HH];
__device__ float g_M[NHD * NQ];
__device__ __align__(256) uint4 g_Xbh4[NW32 / 4];   // X fp16, fragment-major [g][kx][ks][lane][word]
__device__ __align__(16) __half g_Upk[NQ * BB * NHD * EE];  // U fp16: [q][b][n*64+e]
__device__ __align__(16) __half g_Wth[EE * CC];     // W^T hi fp16: [eo][f=n*64+e]
__device__ __align__(16) __half g_Wtl[EE * CC];     // W^T lo

__device__ __forceinline__ float fexp2(float x) {
    float y; asm("ex2.approx.ftz.f32 %0, %1;" : "=f"(y) : "f"(x)); return y;
}
__device__ __forceinline__ uint32_t smem_u32(const void* p) {
    uint32_t a;
    asm("{ .reg .u64 t; cvta.to.shared.u64 t, %1; cvt.u32.u64 %0, t; }" : "=r"(a) : "l"(p));
    return a;
}
__device__ __forceinline__ void cpa16(uint32_t dst, const void* src) {
    asm volatile("cp.async.cg.shared.global [%0], [%1], 16;" :: "r"(dst), "l"(src));
}
__device__ __forceinline__ void mma16816h(float* c, const uint4& a, const uint2& b) {
    asm volatile(
        "mma.sync.aligned.m16n8k16.row.col.f32.f16.f16.f32 "
        "{%0,%1,%2,%3}, {%4,%5,%6,%7}, {%8,%9}, {%0,%1,%2,%3};"
        : "+f"(c[0]), "+f"(c[1]), "+f"(c[2]), "+f"(c[3])
        : "r"(a.x), "r"(a.y), "r"(a.z), "r"(a.w), "r"(b.x), "r"(b.y));
}

// ---------------------------------------------------------------------------
// Fused X fragment-pack + W split.
// X word index o: [g 64][kx 48][ks 3][lane 32][word 2]
__global__ void k_prep_xw(const float* __restrict__ hs, const float* __restrict__ wfc) {
    if (blockIdx.x < NW32 / 256) {
        int o = blockIdx.x * 256 + threadIdx.x;
        int word = o & 1;
        int lane = (o >> 1) & 31;
        int t2 = o >> 6;          // [g][kx][ks]
        int ks = t2 % 3;
        int t3 = t2 / 3;
        int kx = t3 % 48;
        int g  = t3 / 48;
        int n8 = lane >> 2;
        int kk0 = word * 8 + (lane & 3) * 2;
        int c = g * 8 + n8;
        int b = c >> 6, e = c & 63;
        int k = kx * 48 + ks * 16 + kk0;
        float x0 = hs[(b * NQ + k) * EE + e];
        float x1 = hs[(b * NQ + k + 1) * EE + e];
        __half2 h = __floats2half2_rn(x0, x1);
        ((uint32_t*)g_Xbh4)[o] = *(uint32_t*)&h;
    } else {
        int o = (blockIdx.x - NW32 / 256) * 256 + threadIdx.x;
        if (o >= NWW) return;
        int eo = o >> 9, f = o & 511;
        int n = f >> 6, e = f & 63;
        float v = wfc[eo * CC + e * NHD + n];
        __half h = __float2half(v);
        g_Wth[o] = h;
        g_Wtl[o] = __float2half(v - __half2float(h));
    }
}

__global__ void k_table(const float* __restrict__ wsig) {
    int o = blockIdx.x * blockDim.x + threadIdx.x;
    if (o >= NHD * TT) return;
    int n = o / TT, r = o - n * TT;
    int dxi = r / TW, dyi = r - dxi * TW;
    float dx = (float)(dxi - 47), dy = (float)(dyi - 47);
    const float* w = wsig + n * 5;
    g_S[o] = (w[0]*dx + w[1]*dy + w[2]*dx*dx + w[3]*dy*dy + w[4]*dx*dy) * LOG2E;
}

__global__ void k_colmax() {
    int o = blockIdx.x * blockDim.x + threadIdx.x;
    if (o >= NHD * TW * HH) return;
    int n = o / (TW * HH), r = o - n * TW * HH;
    int dxi = r / HH, j = r - dxi * HH;
    const float* row = g_S + n * TT + dxi * TW + (47 - j);
    float m = -1e30f;
    #pragma unroll 8
    for (int l = 0; l < HH; l++) m = fmaxf(m, row[l]);
    g_cm[o] = m;
}

__global__ void k_rowmax() {
    int o = blockIdx.x * blockDim.x + threadIdx.x;
    if (o >= NHD * NQ) return;
    int n = o / NQ, r = o - n * NQ;
    int i = r / HH, j = r - i * HH;
    float m = -1e30f;
    #pragma unroll 8
    for (int k = 0; k < WW; k++)
        m = fmaxf(m, g_cm[(n * TW + (k - i + 47)) * HH + j]);
    g_M[o] = m;
}

// ---------------------------------------------------------------------------
// Dynamic smem layout (bytes)
#define SM_STAB 0                 // 51*95*4 = 19380
#define SM_Z    19392             // 128*4 = 512
#define SM_KEEP 19904             // keep[48] | list[48] @+64 | cnt @+128
#define SM_BUF  20480
#define BUFSZ   36864             // Ah 12K | Bh 24K
#define OFF_BH  12288
#define SMEM_TOTAL (SM_BUF + 2 * BUFSZ)   // 94208

// mma.sync fp16 attention GEMM with Gaussian row skipping.
// Block = (q-tile 128, head, col-half 256), 256 threads.
__global__ __launch_bounds__(256, 1) void k_attn() {
    extern __shared__ char smem[];
    const uint32_t sb = smem_u32(smem);
    const int t = threadIdx.x;
    const int w = t >> 5, l = t & 31;
    const int q0 = blockIdx.x * QT;
    const int n  = blockIdx.y;
    const int chalf = blockIdx.z;
    const int i0 = q0 / HH;
    const int d0 = 44 - i0;

    // stage 51-row score-table slice
    float* Stab = (float*)(smem + SM_STAB);
    for (int idx = t; idx < 51 * TW; idx += 256) {
        int r = idx / TW, c = idx - r * TW;
        int dxi = r + d0;
        Stab[idx] = (dxi >= 0 && dxi < TW) ? g_S[n * TT + dxi * TW + c] : -1e30f;
    }

    // ---- row-skip mask: keep[kx]=1 iff some query sees mass > 2^-25 ----
    unsigned char* keep = (unsigned char*)(smem + SM_KEEP);
    unsigned char* list = keep + 64;
    int* pcnt = (int*)(keep + 128);
    if (t < 48) keep[t] = 0;
    __syncthreads();
    {
        const int qq = t & 127, hf = t >> 7;
        const int qg2 = q0 + qq;
        const int qi2 = qg2 / HH, qj2 = qg2 - qi2 * HH;
        const float M2x = g_M[n * NQ + qg2];
        const float* cmb = g_cm + ((size_t)(n * TW + 47 - qi2)) * HH + qj2;
        #pragma unroll 4
        for (int kx = hf * 24; kx < hf * 24 + 24; kx++)
            if (cmb[(size_t)kx * HH] - M2x > -25.f) keep[kx] = 1;
    }
    __syncthreads();
    if (t == 0) {
        int c2 = 0;
        #pragma unroll 8
        for (int kx = 0; kx < 48; kx++) if (keep[kx]) list[c2++] = kx;
        *pcnt = c2;
    }
    __syncthreads();
    const int cnt = *pcnt;

    // producer constants: warp w owns A rows [w*16, w*16+16); lane rows r0, r0+8
    const int r0 = w * 16 + (l >> 2);
    const int r1 = r0 + 8;
    const int qa = q0 + r0, qb = q0 + r1;
    const int qi0 = qa / HH, qj0 = qa - qi0 * HH;
    const int qi1 = qb / HH, qj1 = qb - qi1 * HH;
    const float* Sq0 = Stab + (47 - qi0 - d0) * TW + (47 - qj0);
    const float* Sq1 = Stab + (47 - qi1 - d0) * TW + (47 - qj1);
    const float M20 = g_M[n * NQ + qa];
    const float M21 = g_M[n * NQ + qb];
    float z0 = 0.f, z1 = 0.f;
    const int kbase = (l & 3) * 2;

    // cp.async: thread handles segment seg (one 8-col group), 6x16B per chunk
    const int seg = t >> 3, uu = t & 7;
    const char* srcH = (const char*)g_Xbh4 + ((size_t)(chalf * 32 + seg) * 48) * 768;

    float acc[4][8][4];
    #pragma unroll
    for (int m = 0; m < 4; m++)
        #pragma unroll
        for (int nn = 0; nn < 8; nn++)
            #pragma unroll
            for (int cdx = 0; cdx < 4; cdx++) acc[m][nn][cdx] = 0.f;

    const int wm = w >> 2, wn = w & 3;

    auto produce = [&](int kx, int buf) {
        char* Ah = smem + SM_BUF + buf * BUFSZ;
        const int kxTW = kx * TW;
        #pragma unroll
        for (int ks = 0; ks < 3; ks++) {
            const int ky = ks * 16 + kbase;
            float pa0 = fexp2(Sq0[kxTW + ky]     - M20);
            float pa1 = fexp2(Sq0[kxTW + ky + 1] - M20);
            float pa8 = fexp2(Sq0[kxTW + ky + 8] - M20);
            float pa9 = fexp2(Sq0[kxTW + ky + 9] - M20);
            float pb0 = fexp2(Sq1[kxTW + ky]     - M21);
            float pb1 = fexp2(Sq1[kxTW + ky + 1] - M21);
            float pb8 = fexp2(Sq1[kxTW + ky + 8] - M21);
            float pb9 = fexp2(Sq1[kxTW + ky + 9] - M21);
            z0 += pa0 + pa1 + pa8 + pa9;
            z1 += pb0 + pb1 + pb8 + pb9;
            __half2 h0 = __floats2half2_rn(pa0, pa1);   // row r0, k/k+1
            __half2 h1 = __floats2half2_rn(pb0, pb1);   // row r1
            __half2 h2 = __floats2half2_rn(pa8, pa9);   // row r0, k+8
            __half2 h3 = __floats2half2_rn(pb8, pb9);   // row r1, k+8
            const uint32_t off = (uint32_t)(((w * 3 + ks) * 32 + l) * 16);
            *(uint4*)(Ah + off) = make_uint4(*(uint32_t*)&h0, *(uint32_t*)&h1,
                                             *(uint32_t*)&h2, *(uint32_t*)&h3);
        }
        const uint32_t dBh = sb + SM_BUF + buf * BUFSZ + OFF_BH + seg * 768;
        const char* sH = srcH + (size_t)kx * 768;
        #pragma unroll
        for (int i = 0; i < 6; i++) {
            int u16 = (uu + i * 8) * 16;
            cpa16(dBh + u16, sH + u16);
        }
        asm volatile("cp.async.commit_group;" ::: "memory");
    };

    produce(list[0], 0);

    for (int ic = 0; ic < cnt; ic++) {
        const int buf = ic & 1;
        if (ic + 1 < cnt) {
            produce(list[ic + 1], buf ^ 1);
            asm volatile("cp.async.wait_group 1;" ::: "memory");
        } else {
            asm volatile("cp.async.wait_group 0;" ::: "memory");
        }
        __syncthreads();

        const uint4* AhP = (const uint4*)(smem + SM_BUF + buf * BUFSZ);
        const uint2* BhP = (const uint2*)(smem + SM_BUF + buf * BUFSZ + OFF_BH);

        #pragma unroll
        for (int ks = 0; ks < 3; ks++) {
            uint4 ah[4];
            #pragma unroll
            for (int m = 0; m < 4; m++)
                ah[m] = AhP[((wm * 4 + m) * 3 + ks) * 32 + l];
            uint2 bh[8];
            #pragma unroll
            for (int nn = 0; nn < 8; nn++)
                bh[nn] = BhP[((wn * 8 + nn) * 3 + ks) * 32 + l];
            #pragma unroll
            for (int m = 0; m < 4; m++)
                #pragma unroll
                for (int nn = 0; nn < 8; nn++)
                    mma16816h(acc[m][nn], ah[m], bh[nn]);
        }
        __syncthreads();
    }

    z0 += __shfl_xor_sync(0xFFFFFFFFu, z0, 1);
    z0 += __shfl_xor_sync(0xFFFFFFFFu, z0, 2);
    z1 += __shfl_xor_sync(0xFFFFFFFFu, z1, 1);
    z1 += __shfl_xor_sync(0xFFFFFFFFu, z1, 2);
    float* sZ = (float*)(smem + SM_Z);
    if ((l & 3) == 0) { sZ[r0] = z0; sZ[r1] = z1; }
    __syncthreads();

    // epilogue: scale by 1/Z, store fp16 to g_Upk[q][b][n*64+e]
    const int bcol = chalf * 4 + wn;
    #pragma unroll
    for (int m = 0; m < 4; m++) {
        const int rowa = wm * 64 + m * 16 + (l >> 2);
        const float rza = 1.0f / sZ[rowa];
        const float rzb = 1.0f / sZ[rowa + 8];
        __half* dsta = g_Upk + (size_t)(q0 + rowa) * (BB * NHD * EE) + bcol * (NHD * EE) + n * EE;
        __half* dstb = dsta + (size_t)8 * (BB * NHD * EE);
        #pragma unroll
        for (int nn = 0; nn < 8; nn++) {
            const int e = nn * 8 + (l & 3) * 2;
            __half2 va = __floats2half2_rn(acc[m][nn][0] * rza, acc[m][nn][1] * rza);
            __half2 vb = __floats2half2_rn(acc[m][nn][2] * rzb, acc[m][nn][3] * rzb);
            *(__half2*)(dsta + e) = va;
            *(__half2*)(dstb + e) = vb;
        }
    }
}

// ---------------------------------------------------------------------------
// Final projection via fp16 mma (unchanged from R9).
__global__ __launch_bounds__(256) void k_proj(const float* __restrict__ bfc,
                                              float* __restrict__ out) {
    __shared__ __half As[128][72];
    __shared__ __half Whs[64][72];
    __shared__ __half Wls[64][72];
    const int t = threadIdx.x;
    const int w = t >> 5, l = t & 31;
    const int q0 = blockIdx.x * 128;
    const int b  = blockIdx.y;
    const int wm = w >> 1, wn = w & 1;

    float acc[2][4][4];
    #pragma unroll
    for (int m = 0; m < 2; m++)
        #pragma unroll
        for (int nt = 0; nt < 4; nt++)
            #pragma unroll
            for (int c = 0; c < 4; c++) acc[m][nt][c] = 0.f;

    for (int fck = 0; fck < 8; fck++) {
        __syncthreads();
        #pragma unroll
        for (int i = 0; i < 4; i++) {
            int idx = t * 4 + i;
            int row = idx >> 3, u = idx & 7;
            uint4 v = *(const uint4*)(g_Upk + (size_t)(q0 + row) * 4096 + b * 512 + fck * 64 + u * 8);
            *(uint4*)(&As[row][u * 8]) = v;
        }
        #pragma unroll
        for (int i = 0; i < 2; i++) {
            int idx = t * 2 + i;
            int eo = idx >> 3, u = idx & 7;
            uint4 vh = *(const uint4*)(g_Wth + eo * 512 + fck * 64 + u * 8);
            uint4 vl = *(const uint4*)(g_Wtl + eo * 512 + fck * 64 + u * 8);
            *(uint4*)(&Whs[eo][u * 8]) = vh;
            *(uint4*)(&Wls[eo][u * 8]) = vl;
        }
        __syncthreads();

        #pragma unroll
        for (int ks = 0; ks < 4; ks++) {
            const int kb = ks * 16;
            uint4 a[2];
            #pragma unroll
            for (int m = 0; m < 2; m++) {
                const int row = wm * 32 + m * 16 + (l >> 2);
                a[m].x = *(const uint32_t*)(&As[row][kb + (l & 3) * 2]);
                a[m].y = *(const uint32_t*)(&As[row + 8][kb + (l & 3) * 2]);
                a[m].z = *(const uint32_t*)(&As[row][kb + 8 + (l & 3) * 2]);
                a[m].w = *(const uint32_t*)(&As[row + 8][kb + 8 + (l & 3) * 2]);
            }
            #pragma unroll
            for (int nt = 0; nt < 4; nt++) {
                const int eo = wn * 32 + nt * 8 + (l >> 2);
                uint2 bh, bl;
                bh.x = *(const uint32_t*)(&Whs[eo][kb + (l & 3) * 2]);
                bh.y = *(const uint32_t*)(&Whs[eo][kb + 8 + (l & 3) * 2]);
                bl.x = *(const uint32_t*)(&Wls[eo][kb + (l & 3) * 2]);
                bl.y = *(const uint32_t*)(&Wls[eo][kb + 8 + (l & 3) * 2]);
                #pragma unroll
                for (int m = 0; m < 2; m++) {
                    mma16816h(acc[m][nt], a[m], bh);
                    mma16816h(acc[m][nt], a[m], bl);
                }
            }
        }
    }

    #pragma unroll
    for (int m = 0; m < 2; m++) {
        const int row = wm * 32 + m * 16 + (l >> 2);
        #pragma unroll
        for (int nt = 0; nt < 4; nt++) {
            const int eo = wn * 32 + nt * 8 + (l & 3) * 2;
            float2 v0 = make_float2(acc[m][nt][0] + bfc[eo], acc[m][nt][1] + bfc[eo + 1]);
            float2 v1 = make_float2(acc[m][nt][2] + bfc[eo], acc[m][nt][3] + bfc[eo + 1]);
            *(float2*)(out + (size_t)(b * NQ + q0 + row) * EE + eo) = v0;
            *(float2*)(out + (size_t)(b * NQ + q0 + row + 8) * EE + eo) = v1;
        }
    }
}

// ---------------------------------------------------------------------------
extern "C" void kernel_launch(void* const* d_in, const int* in_sizes, int n_in,
                              void* d_out, int out_size) {
    const float* hs   = (const float*)d_in[0];
    const float* wsig = (const float*)d_in[3];
    const float* wfc  = (const float*)d_in[5];
    const float* bfc  = (const float*)d_in[6];
    float* out = (float*)d_out;

    cudaFuncSetAttribute(k_attn, cudaFuncAttributeMaxDynamicSharedMemorySize, SMEM_TOTAL);

    k_prep_xw<<<NW32 / 256 + (NWW + 255) / 256, 256>>>(hs, wfc);
    k_table<<<(NHD * TT + 255) / 256, 256>>>(wsig);
    k_colmax<<<(NHD * TW * HH + 255) / 256, 256>>>();
    k_rowmax<<<(NHD * NQ + 255) / 256, 256>>>();

    dim3 ga(NQ / QT, NHD, 2);   // (18, 8, 2)
    k_attn<<<ga, 256, SMEM_TOTAL>>>();

    dim3 gp(NQ / 128, BB);      // (18, 8)
    k_proj<<<gp, 256>>>(bfc, out);
}